// round 1
// baseline (speedup 1.0000x reference)
#include <cuda_runtime.h>
#include <cstdint>

// CRF log-partition (forward algorithm) on GB300.
// Shapes fixed by the dataset: B=64, T=2048, C=1, N=128.
//
// One CTA per batch element. 128 threads; thread j owns output tag j and
// keeps E[k] = exp(transitions[k][j]) resident in 128 registers.
// State kept in scaled-exp domain: alpha_j = M + log(q_j), q_j in registers.
// Per step:  s_j = sum_k q_k * E[k][j]   (plain FFMA matvec, q broadcast via smem)
//            q'_j = s_j * exp2(em_j*log2e - log2(bm)),  M += ln(bm)
// with bm = blockmax(q) for renormalization (redux.sync.max.u32 on the
// positive-float bit pattern, which is order-preserving).

#define NTAGS 128
#define TMAXR 2048
#define LOG2E_F 1.4426950408889634f
#define LN2_F   0.6931471805599453f

__global__ void __launch_bounds__(128, 1)
crf_logZ_kernel(const float* __restrict__ emissions,    // [B, T, 1, N]
                const int*   __restrict__ token_sizes,  // [B]
                const float* __restrict__ transitions,  // [1,1,N,N] -> [prev k][next j]
                const float* __restrict__ head_t,       // [N]
                const float* __restrict__ last_t,       // [N]
                float* __restrict__ out)                // [B, 1]
{
    __shared__ __align__(16) float p[2][NTAGS];   // broadcast buffer for q, double-buffered
    __shared__ float wmax[2][4];                  // per-warp maxes, double-buffered
    __shared__ float redbuf[4];                   // final reduction

    const int b    = blockIdx.x;
    const int j    = threadIdx.x;
    const int lane = j & 31;
    const int warp = j >> 5;
    const int len  = token_sizes[b];
    const float* emb = emissions + (size_t)b * TMAXR * NTAGS;

    // ---- Load E column j into registers: E[k] = exp(trans[k][j]) ----
    float E[NTAGS];
#pragma unroll
    for (int k = 0; k < NTAGS; ++k)
        E[k] = exp2f(transitions[k * NTAGS + j] * LOG2E_F);

    // ---- init: alpha0 = head + em[0]; q = exp(alpha0 - m0); M = m0 ----
    float a0 = head_t[j] + emb[j];
    p[0][j] = a0;
    __syncthreads();
    float m0 = -3.4e38f;
#pragma unroll
    for (int k = 0; k < NTAGS; ++k) m0 = fmaxf(m0, p[0][k]);
    __syncthreads();

    float q = exp2f((a0 - m0) * LOG2E_F);
    float M = m0;

    // ---- emission prefetch pipeline (depth 2). Rows up to T-1 always exist. ----
    float em_c = emb[1 * NTAGS + j];   // emission for t=1
    float em_n = emb[2 * NTAGS + j];   // emission for t=2

    int buf = 0;
    for (int t = 1; t < len; ++t) {
        // publish q + per-warp max (both land before the barrier)
        p[buf][j] = q;
        unsigned um;
        asm volatile("redux.sync.max.u32 %0, %1, 0xffffffff;"
                     : "=r"(um) : "r"(__float_as_uint(q)));
        if (lane == 0) wmax[buf][warp] = __uint_as_float(um);
        __syncthreads();

        // block max of current q (4-word read; overlaps the matvec)
        float bm = fmaxf(fmaxf(wmax[buf][0], wmax[buf][1]),
                         fmaxf(wmax[buf][2], wmax[buf][3]));
        float lbm = log2f(bm);

        // matvec: s_j = sum_k q_k * E[k][j]; 4 independent accumulator chains
        float s0 = 0.f, s1 = 0.f, s2 = 0.f, s3 = 0.f;
        const float4* pv4 = (const float4*)p[buf];
#pragma unroll
        for (int k4 = 0; k4 < NTAGS / 4; ++k4) {
            float4 pv = pv4[k4];
            s0 = fmaf(pv.x, E[4 * k4 + 0], s0);
            s1 = fmaf(pv.y, E[4 * k4 + 1], s1);
            s2 = fmaf(pv.z, E[4 * k4 + 2], s2);
            s3 = fmaf(pv.w, E[4 * k4 + 3], s3);
        }
        float s = (s0 + s1) + (s2 + s3);

        // prefetch emission for t+2 (clamped; padded rows always allocated)
        int tn = t + 2; if (tn > TMAXR - 1) tn = TMAXR - 1;
        float em_f = __ldg(emb + (size_t)tn * NTAGS + j);

        // rescale: q' = s * exp(em - ln bm);  M += ln bm
        q = s * exp2f(fmaf(em_c, LOG2E_F, -lbm));
        M = fmaf(lbm, LN2_F, M);

        em_c = em_n;
        em_n = em_f;
        buf ^= 1;
    }

    // ---- terminate: out[b] = M + log(sum_j q_j * exp(last_t[j])) ----
    float v = q * exp2f(last_t[j] * LOG2E_F);
#pragma unroll
    for (int o = 16; o > 0; o >>= 1)
        v += __shfl_xor_sync(0xffffffff, v, o);
    if (lane == 0) redbuf[warp] = v;
    __syncthreads();
    if (j == 0) {
        float sv = (redbuf[0] + redbuf[1]) + (redbuf[2] + redbuf[3]);
        out[b] = fmaf(log2f(sv), LN2_F, M);
    }
}

extern "C" void kernel_launch(void* const* d_in, const int* in_sizes, int n_in,
                              void* d_out, int out_size) {
    const float* emissions   = (const float*)d_in[0];  // [64,2048,1,128]
    const int*   token_sizes = (const int*)  d_in[1];  // [64]
    const float* transitions = (const float*)d_in[2];  // [1,1,128,128]
    const float* head_t      = (const float*)d_in[3];  // [1,1,128]
    const float* last_t      = (const float*)d_in[4];  // [1,1,128]
    float* out = (float*)d_out;                        // [64,1]

    crf_logZ_kernel<<<64, 128>>>(emissions, token_sizes, transitions,
                                 head_t, last_t, out);
}

// round 2
// speedup vs baseline: 1.2049x; 1.2049x over previous
#include <cuda_runtime.h>
#include <cstdint>

// CRF log-partition (forward algorithm). B=64, T=2048, C=1, N=128.
//
// One CTA per batch. 128 threads; thread j owns output tag j with
// E[k] = exp(trans[k][j]) resident in 64 packed f32x2 registers.
// State in scaled-exp domain: alpha_j = m0 + Mint*ln2 + ln(q_j).
// Per step: s_j = sum_k q_k * E[k][j]  (fma.rn.f32x2 matvec, q via smem
// broadcast read as ulonglong2), then q' = s * 2^{-e} * exp(em), where
// e = exponent(q[0]) — an exact power-of-2 renorm (q's spread across tags
// is bounded by ~e^11, so q[0] tracks the max closely enough to prevent
// overflow/underflow). Mint accumulates e exactly as an integer.

#define NTAGS 128
#define TMAXR 2048
#define LOG2E_F 1.4426950408889634f

typedef unsigned long long ull;

__device__ __forceinline__ ull fma2(ull a, ull b, ull c) {
    ull d;
    asm("fma.rn.f32x2 %0, %1, %2, %3;" : "=l"(d) : "l"(a), "l"(b), "l"(c));
    return d;
}
__device__ __forceinline__ ull add2(ull a, ull b) {
    ull d;
    asm("add.rn.f32x2 %0, %1, %2;" : "=l"(d) : "l"(a), "l"(b));
    return d;
}
__device__ __forceinline__ ull pk(float lo, float hi) {
    ull v;
    asm("mov.b64 %0, {%1, %2};" : "=l"(v) : "f"(lo), "f"(hi));
    return v;
}
__device__ __forceinline__ float2 unpk(ull v) {
    float2 f;
    asm("mov.b64 {%0, %1}, %2;" : "=f"(f.x), "=f"(f.y) : "l"(v));
    return f;
}

__global__ void __launch_bounds__(128, 1)
crf_logZ_kernel(const float* __restrict__ emissions,    // [B, T, 1, N]
                const int*   __restrict__ token_sizes,  // [B]
                const float* __restrict__ transitions,  // [1,1,N,N] (prev k, next j)
                const float* __restrict__ head_t,       // [N]
                const float* __restrict__ last_t,       // [N]
                float* __restrict__ out)                // [B, 1]
{
    __shared__ __align__(16) float p[2][NTAGS];   // q broadcast buffer (double-buffered)
    __shared__ float redbuf[4];

    const int b    = blockIdx.x;
    const int j    = threadIdx.x;
    const int lane = j & 31;
    const int warp = j >> 5;
    const int len  = token_sizes[b];
    const float* emb = emissions + (size_t)b * TMAXR * NTAGS;

    // ---- E column j, packed as 64 f32x2 pairs over consecutive k ----
    ull Epk[NTAGS / 2];
#pragma unroll
    for (int i = 0; i < NTAGS / 2; ++i) {
        float e0 = exp2f(transitions[(2 * i + 0) * NTAGS + j] * LOG2E_F);
        float e1 = exp2f(transitions[(2 * i + 1) * NTAGS + j] * LOG2E_F);
        Epk[i] = pk(e0, e1);
    }

    // ---- init: alpha0 = head + em[0]; q = exp(alpha0 - m0) ----
    float a0 = head_t[j] + emb[j];
    p[0][j] = a0;
    __syncthreads();
    float m0 = -3.4e38f;
#pragma unroll
    for (int k = 0; k < NTAGS; ++k) m0 = fmaxf(m0, p[0][k]);
    __syncthreads();

    float q   = exp2f((a0 - m0) * LOG2E_F);
    int  Mint = 0;

    // ---- emission prefetch pipeline, depth 3 (rows < T always allocated) ----
    float em_c  = emb[1 * NTAGS + j];
    float em_n  = emb[2 * NTAGS + j];
    float em_n2 = emb[3 * NTAGS + j];

    int buf = 0;
    for (int t = 1; t < len; ++t) {
        p[buf][j] = q;
        __syncthreads();

        // off-critical-path scalar work (overlaps LDS/matvec)
        float ex = exp2f(em_c * LOG2E_F);

        const ulonglong2* pv = (const ulonglong2*)p[buf];
        ulonglong2 v0 = pv[0];

        // power-of-2 renorm keyed off q[0] (low word of v0.x)
        unsigned e0bits = ((unsigned)v0.x) >> 23;
        if (e0bits == 0u) e0bits = 127u;                  // paranoia guard
        int   e     = (int)e0bits - 127;
        float scale = __uint_as_float((254u - e0bits) << 23);   // 2^{-e}
        Mint += e;
        float sc2 = scale * ex;

        // matvec: 64 packed FFMA2, 4 independent accumulator chains
        ull s0 = 0ull, s1 = 0ull, s2 = 0ull, s3 = 0ull;
#pragma unroll
        for (int i = 0; i < NTAGS / 4; ++i) {
            ulonglong2 v = (i == 0) ? v0 : pv[i];
            if (i & 1) {
                s2 = fma2(v.x, Epk[2 * i + 0], s2);
                s3 = fma2(v.y, Epk[2 * i + 1], s3);
            } else {
                s0 = fma2(v.x, Epk[2 * i + 0], s0);
                s1 = fma2(v.y, Epk[2 * i + 1], s1);
            }
        }
        ull sa = add2(add2(s0, s1), add2(s2, s3));
        float2 sf = unpk(sa);
        float s = sf.x + sf.y;

        // prefetch emission for t+3
        int tn = t + 3; if (tn > TMAXR - 1) tn = TMAXR - 1;
        float em_f = __ldg(emb + (size_t)tn * NTAGS + j);

        q = s * sc2;

        em_c = em_n; em_n = em_n2; em_n2 = em_f;
        buf ^= 1;
    }

    // ---- terminate: out[b] = m0 + Mint*ln2 + ln(sum_j q_j * exp(last_j)) ----
    float v = q * exp2f(last_t[j] * LOG2E_F);
#pragma unroll
    for (int o = 16; o > 0; o >>= 1)
        v += __shfl_xor_sync(0xffffffff, v, o);
    if (lane == 0) redbuf[warp] = v;
    __syncthreads();
    if (j == 0) {
        float sv = (redbuf[0] + redbuf[1]) + (redbuf[2] + redbuf[3]);
        double r = (double)m0 + (double)Mint * 0.6931471805599453094
                 + log((double)sv);
        out[b] = (float)r;
    }
}

extern "C" void kernel_launch(void* const* d_in, const int* in_sizes, int n_in,
                              void* d_out, int out_size) {
    const float* emissions   = (const float*)d_in[0];  // [64,2048,1,128]
    const int*   token_sizes = (const int*)  d_in[1];  // [64]
    const float* transitions = (const float*)d_in[2];  // [1,1,128,128]
    const float* head_t      = (const float*)d_in[3];  // [1,1,128]
    const float* last_t      = (const float*)d_in[4];  // [1,1,128]
    float* out = (float*)d_out;                        // [64,1]

    crf_logZ_kernel<<<64, 128>>>(emissions, token_sizes, transitions,
                                 head_t, last_t, out);
}

// round 4
// speedup vs baseline: 1.6250x; 1.3487x over previous
#include <cuda_runtime.h>
#include <cuda_bf16.h>
#include <cstdint>

// CRF log-partition (forward algorithm). B=64, T=2048, C=1, N=128.
//
// One CTA per batch, 128 threads, thread j owns output tag j.
// E column j resident as 64 bf16x2 registers. State in scaled-exp domain:
// alpha_j = m0 + Mint*ln2 + ln(q_j), q published per step as bf16 via smem.
// Matvec: 64 HFMA2.BF16 per thread (rt 2 -> 128-cyc fma floor, half of fp32).
// Renorm: exact power-of-2 scale keyed on published q0's bf16 exponent
// (one-step-delayed self-correcting; bf16's 2^+-126 range absorbs the slack).
// Mint accumulates the exponent exactly as an integer.

#define NTAGS 128
#define TMAXR 2048
#define LOG2E_F 1.4426950408889634f

typedef __nv_bfloat16  bf16;
typedef __nv_bfloat162 bf16x2;

__device__ __forceinline__ bf16x2 as_bf2(unsigned u) {
    bf16x2 r = *reinterpret_cast<bf16x2*>(&u);
    return r;
}

__global__ void __launch_bounds__(128, 1)
crf_logZ_kernel(const float* __restrict__ emissions,    // [B, T, 1, N]
                const int*   __restrict__ token_sizes,  // [B]
                const float* __restrict__ transitions,  // [1,1,N,N] (prev k, next j)
                const float* __restrict__ head_t,       // [N]
                const float* __restrict__ last_t,       // [N]
                float* __restrict__ out)                // [B, 1]
{
    __shared__ __align__(16) bf16 ph[2][NTAGS];   // q broadcast buffer, double-buffered
    __shared__ float redbuf[4];

    const int b    = blockIdx.x;
    const int j    = threadIdx.x;
    const int lane = j & 31;
    const int warp = j >> 5;
    const int len  = token_sizes[b];
    const float* emb = emissions + (size_t)b * TMAXR * NTAGS;

    // ---- E column j as 64 bf16x2 pairs over consecutive k ----
    bf16x2 Eh[NTAGS / 2];
#pragma unroll
    for (int i = 0; i < NTAGS / 2; ++i) {
        float e0 = exp2f(transitions[(2 * i + 0) * NTAGS + j] * LOG2E_F);
        float e1 = exp2f(transitions[(2 * i + 1) * NTAGS + j] * LOG2E_F);
        Eh[i] = __floats2bfloat162_rn(e0, e1);
    }

    // ---- init: alpha0 = head + em[0]; m0 = blockmax(alpha0); q = exp(alpha0-m0) ----
    float a0 = head_t[j] + emb[j];
    float wm = a0;
#pragma unroll
    for (int o = 16; o > 0; o >>= 1)
        wm = fmaxf(wm, __shfl_xor_sync(0xffffffff, wm, o));
    if (lane == 0) redbuf[warp] = wm;
    __syncthreads();
    float m0 = fmaxf(fmaxf(redbuf[0], redbuf[1]), fmaxf(redbuf[2], redbuf[3]));
    __syncthreads();

    bf16 qh  = __float2bfloat16(exp2f((a0 - m0) * LOG2E_F));
    int  Mint = 0;

    // ---- emission pipeline: d_c = exp(em[t]) computed one step early;
    //      raw em prefetched three steps ahead (rows < T always allocated) ----
    float em_a = emb[2 * NTAGS + j];                 // em[t+1] source
    float em_b = emb[3 * NTAGS + j];                 // em[t+2] source
    float d_c  = exp2f(emb[1 * NTAGS + j] * LOG2E_F);  // d for t = 1

    int buf = 0;
    for (int t = 1; t < len; ++t) {
        ph[buf][j] = qh;
        __syncthreads();

        // renorm scale from published q0's bf16 exponent (broadcast LDS.U16)
        unsigned short q0b = *reinterpret_cast<const unsigned short*>(&ph[buf][0]);
        unsigned eh = ((unsigned)q0b >> 7) & 0xffu;
        float scale = __uint_as_float((254u - eh) << 23);   // 2^(127-eh)
        Mint += (int)eh - 127;
        bf16 hds = __float2bfloat16(d_c * scale);           // off critical path

        // matvec: 64 HFMA2.BF16, 4 bf16x2 accumulator chains
        const uint4* pv = (const uint4*)ph[buf];
        bf16x2 s0 = __floats2bfloat162_rn(0.f, 0.f);
        bf16x2 s1 = s0, s2 = s0, s3 = s0;
#pragma unroll
        for (int i = 0; i < NTAGS / 8; ++i) {
            uint4 v = pv[i];
            s0 = __hfma2(as_bf2(v.x), Eh[4 * i + 0], s0);
            s1 = __hfma2(as_bf2(v.y), Eh[4 * i + 1], s1);
            s2 = __hfma2(as_bf2(v.z), Eh[4 * i + 2], s2);
            s3 = __hfma2(as_bf2(v.w), Eh[4 * i + 3], s3);
        }

        // prefetch em[t+3]; compute d for t+1 (both off critical path)
        int tn = t + 3; if (tn > TMAXR - 1) tn = TMAXR - 1;
        float em_f = __ldg(emb + (size_t)tn * NTAGS + j);
        float d_n  = exp2f(em_a * LOG2E_F);

        // reduce tree + publish-value multiply
        bf16x2 u0 = __hadd2(s0, s1);
        bf16x2 u1 = __hadd2(s2, s3);
        bf16x2 u2 = __hadd2(u0, u1);
        bf16 sh = __hadd(__low2bfloat16(u2), __high2bfloat16(u2));
        qh = __hmul(sh, hds);

        em_a = em_b; em_b = em_f; d_c = d_n;
        buf ^= 1;
    }

    // ---- terminate: out[b] = m0 + Mint*ln2 + ln(sum_j q_j * exp(last_j)) ----
    float v = __bfloat162float(qh) * exp2f(last_t[j] * LOG2E_F);
#pragma unroll
    for (int o = 16; o > 0; o >>= 1)
        v += __shfl_xor_sync(0xffffffff, v, o);
    __syncthreads();                 // redbuf reuse
    if (lane == 0) redbuf[warp] = v;
    __syncthreads();
    if (j == 0) {
        float sv = (redbuf[0] + redbuf[1]) + (redbuf[2] + redbuf[3]);
        double r = (double)m0 + (double)Mint * 0.6931471805599453094
                 + log((double)sv);
        out[b] = (float)r;
    }
}

extern "C" void kernel_launch(void* const* d_in, const int* in_sizes, int n_in,
                              void* d_out, int out_size) {
    const float* emissions   = (const float*)d_in[0];  // [64,2048,1,128]
    const int*   token_sizes = (const int*)  d_in[1];  // [64]
    const float* transitions = (const float*)d_in[2];  // [1,1,128,128]
    const float* head_t      = (const float*)d_in[3];  // [1,1,128]
    const float* last_t      = (const float*)d_in[4];  // [1,1,128]
    float* out = (float*)d_out;                        // [64,1]

    crf_logZ_kernel<<<64, 128>>>(emissions, token_sizes, transitions,
                                 head_t, last_t, out);
}